// round 12
// baseline (speedup 1.0000x reference)
#include <cuda_runtime.h>
#include <cstdint>

#define S_LEN 2048
#define DK 64
#define BM 128
#define BN 64
#define NBH 32
#define CTX_ELEMS ((size_t)NBH * S_LEN * DK)

#define RS 144   // smem row stride in bytes -> conflict-free LDSM

#define OFF_QHI 0
#define OFF_QLO (BM * RS)
#define OFF_KHI (2 * BM * RS)
#define OFF_KLO (OFF_KHI + BN * RS)
#define OFF_VHI (OFF_KLO + BN * RS)
#define OFF_VLO (OFF_VHI + BN * RS)
#define OFF_SINV (OFF_VLO + BN * RS)            // 128 floats: per-row 1/lsum
#define SMEM_TOTAL (OFF_SINV + BM * 4)          // 74240 B -> 2 CTAs/SM

// ---------------------------------------------------------------------------
// helpers
// ---------------------------------------------------------------------------
__device__ __forceinline__ uint32_t smem_u32(const void* p) {
    uint32_t a;
    asm("{ .reg .u64 t; cvta.to.shared.u64 t, %1; cvt.u32.u64 %0, t; }"
        : "=r"(a) : "l"(p));
    return a;
}

__device__ __forceinline__ void ldsm_x4(uint32_t* r, uint32_t addr) {
    asm volatile("ldmatrix.sync.aligned.m8n8.x4.shared.b16 {%0,%1,%2,%3}, [%4];"
        : "=r"(r[0]), "=r"(r[1]), "=r"(r[2]), "=r"(r[3]) : "r"(addr));
}
__device__ __forceinline__ void ldsm_x4t(uint32_t* r, uint32_t addr) {
    asm volatile("ldmatrix.sync.aligned.m8n8.x4.trans.shared.b16 {%0,%1,%2,%3}, [%4];"
        : "=r"(r[0]), "=r"(r[1]), "=r"(r[2]), "=r"(r[3]) : "r"(addr));
}

// pack two f32 -> bf16x2 (a -> low half, b -> high half)
__device__ __forceinline__ uint32_t bf2(float a, float b) {
    uint32_t r;
    asm("cvt.rn.bf16x2.f32 %0, %1, %2;" : "=r"(r) : "f"(b), "f"(a));
    return r;
}
__device__ __forceinline__ float bflo(uint32_t p) { return __uint_as_float(p << 16); }
__device__ __forceinline__ float bfhi(uint32_t p) { return __uint_as_float(p & 0xffff0000u); }

// m16n8k16 bf16 mma, D=C (accumulate in-place)
__device__ __forceinline__ void mma16816(float* c, const uint32_t* a, const uint32_t* b) {
    asm volatile(
        "mma.sync.aligned.m16n8k16.row.col.f32.bf16.bf16.f32 "
        "{%0,%1,%2,%3}, {%4,%5,%6,%7}, {%8,%9}, {%0,%1,%2,%3};"
        : "+f"(c[0]), "+f"(c[1]), "+f"(c[2]), "+f"(c[3])
        : "r"(a[0]), "r"(a[1]), "r"(a[2]), "r"(a[3]), "r"(b[0]), "r"(b[1]));
}

// convert 8 f32 (two float4) -> hi/lo bf16 16B chunks, store linear
__device__ __forceinline__ void cvt_store8(float4 a, float4 b, char* hi_base,
                                           char* lo_base, uint32_t byte_off) {
    float x[8] = {a.x, a.y, a.z, a.w, b.x, b.y, b.z, b.w};
    uint4 hi4, lo4;
    uint32_t* hp = (uint32_t*)&hi4;
    uint32_t* lp = (uint32_t*)&lo4;
    #pragma unroll
    for (int i = 0; i < 4; i++) {
        uint32_t h = bf2(x[2 * i], x[2 * i + 1]);
        hp[i] = h;
        lp[i] = bf2(x[2 * i] - bflo(h), x[2 * i + 1] - bfhi(h));
    }
    *(uint4*)(hi_base + byte_off) = hi4;
    *(uint4*)(lo_base + byte_off) = lo4;
}

// ---------------------------------------------------------------------------
// Fused pass: mma.sync flash attention; writes unnormalized attn, then the
// same CTA normalizes its own 128 rows (+ zero upper triangle) in a tail
// phase that overlaps other CTAs' tensor work. Context written normalized.
// CTA = 256 threads (8 warps), warp w owns rows [w*16, w*16+16).
// ---------------------------------------------------------------------------
__global__ __launch_bounds__(256, 2)
void attn_fused(const float* __restrict__ Qg, const float* __restrict__ Kg,
                const float* __restrict__ Vg, float* __restrict__ out)
{
    extern __shared__ char smc[];
    const uint32_t smb = smem_u32(smc);
    float* sinv = (float*)(smc + OFF_SINV);
    const int tid  = threadIdx.x;
    const int wid  = tid >> 5;
    const int lane = tid & 31;
    const int r    = lane >> 2;     // C/A fragment row-in-group
    const int q    = lane & 3;      // fragment col-group

    const int bh   = blockIdx.y;
    const int qb   = (int)gridDim.x - 1 - (int)blockIdx.x;  // heavy blocks first
    const int row0 = qb * BM;
    const int mrow = wid * 16;

    const float* Qbh = Qg + (size_t)bh * S_LEN * DK;
    const float* Kbh = Kg + (size_t)bh * S_LEN * DK;
    const float* Vbh = Vg + (size_t)bh * S_LEN * DK;
    float* ctx  = out + (size_t)bh * S_LEN * DK;
    float* attn = out + CTX_ELEMS + (size_t)bh * S_LEN * S_LEN;

    // per-lane ldmatrix base offsets
    const uint32_t aQbase = (uint32_t)((mrow + (lane & 15)) * RS + (lane >> 4) * 16);
    const uint32_t bKbase = (uint32_t)(((lane >> 4) * 8 + (lane & 7)) * RS
                                       + ((lane >> 3) & 1) * 16);
    const uint32_t bVbase = (uint32_t)((((lane >> 3) & 1) * 8 + (lane & 7)) * RS
                                       + (lane >> 4) * 16);

    // ---- convert Q tile (2 threads per row, 32 elems each) ----
    {
        int row = tid >> 1, half = tid & 1;
        const float* qrow = Qbh + (size_t)(row0 + row) * DK + half * 32;
        #pragma unroll
        for (int g = 0; g < 4; g++) {
            float4 a = __ldg((const float4*)(qrow + g * 8));
            float4 b = __ldg((const float4*)(qrow + g * 8 + 4));
            cvt_store8(a, b, smc + OFF_QHI, smc + OFF_QLO,
                       (uint32_t)(row * RS + half * 64 + g * 16));
        }
    }

    float oacc[8][4];
    #pragma unroll
    for (int j = 0; j < 8; j++) {
        oacc[j][0] = 0.f; oacc[j][1] = 0.f; oacc[j][2] = 0.f; oacc[j][3] = 0.f;
    }
    float lsum0 = 0.f, lsum1 = 0.f;
    const int grow0  = row0 + mrow + r;         // this thread's first row
    const int rowmax = row0 + mrow + 15;        // warp band's last row

    // K/V gmem positions for this thread (4 threads per row, 16 floats each)
    const int ld_row = tid >> 2;
    const int ld_qt  = tid & 3;

    const int nkb = 2 * qb + 2;
    for (int jb = 0; jb < nkb; jb++) {
        const int c0 = jb * BN;

        // ---- issue gmem loads BEFORE the barrier (latency overlap) ----
        const float* krow = Kbh + (size_t)(c0 + ld_row) * DK + ld_qt * 16;
        const float* vrow = Vbh + (size_t)(c0 + ld_row) * DK + ld_qt * 16;
        float4 k0 = __ldg((const float4*)(krow));
        float4 k1 = __ldg((const float4*)(krow + 4));
        float4 k2 = __ldg((const float4*)(krow + 8));
        float4 k3 = __ldg((const float4*)(krow + 12));
        float4 v0 = __ldg((const float4*)(vrow));
        float4 v1 = __ldg((const float4*)(vrow + 4));
        float4 v2 = __ldg((const float4*)(vrow + 8));
        float4 v3 = __ldg((const float4*)(vrow + 12));

        if (jb) __syncthreads();                // prior tile done with K/V smem

        {
            uint32_t off = (uint32_t)(ld_row * RS + ld_qt * 32);
            cvt_store8(k0, k1, smc + OFF_KHI, smc + OFF_KLO, off);
            cvt_store8(k2, k3, smc + OFF_KHI, smc + OFF_KLO, off + 16);
            cvt_store8(v0, v1, smc + OFF_VHI, smc + OFF_VLO, off);
            cvt_store8(v2, v3, smc + OFF_VHI, smc + OFF_VLO, off + 16);
        }
        __syncthreads();

        if (c0 > rowmax) continue;              // tile fully masked for warp

        // ---- S = Q @ K^T (split-bf16, 3 terms; skip masked 16-key groups) ----
        float sacc[8][4];
        #pragma unroll
        for (int j = 0; j < 8; j++) {
            sacc[j][0] = 0.f; sacc[j][1] = 0.f; sacc[j][2] = 0.f; sacc[j][3] = 0.f;
        }
        #pragma unroll
        for (int ks = 0; ks < 4; ks++) {
            uint32_t ah[4], al[4];
            ldsm_x4(ah, smb + OFF_QHI + aQbase + ks * 32);
            ldsm_x4(al, smb + OFF_QLO + aQbase + ks * 32);
            #pragma unroll
            for (int jp = 0; jp < 4; jp++) {
                if (c0 + jp * 16 > rowmax) continue;   // whole key group masked
                uint32_t kh[4], kl[4];
                uint32_t boff = bKbase + (uint32_t)(jp * 16 * RS + ks * 32);
                ldsm_x4(kh, smb + OFF_KHI + boff);
                ldsm_x4(kl, smb + OFF_KLO + boff);
                mma16816(sacc[2 * jp],     ah, kh);
                mma16816(sacc[2 * jp + 1], ah, kh + 2);
                mma16816(sacc[2 * jp],     ah, kl);
                mma16816(sacc[2 * jp + 1], ah, kl + 2);
                mma16816(sacc[2 * jp],     al, kh);
                mma16816(sacc[2 * jp + 1], al, kh + 2);
            }
        }

        // ---- fused epilogue + PV per 16-key group (skip masked groups) ----
        #pragma unroll
        for (int ks = 0; ks < 4; ks++) {
            if (c0 + ks * 16 > rowmax) continue;       // P == 0 for this group
            uint32_t ah[4], al[4];
            #pragma unroll
            for (int jj = 0; jj < 2; jj++) {
                const int j  = 2 * ks + jj;
                const int cj = c0 + j * 8 + q * 2;
                float p0 = (cj     <= grow0)     ? __expf(sacc[j][0] * 0.125f) : 0.f;
                float p1 = (cj + 1 <= grow0)     ? __expf(sacc[j][1] * 0.125f) : 0.f;
                float p2 = (cj     <= grow0 + 8) ? __expf(sacc[j][2] * 0.125f) : 0.f;
                float p3 = (cj + 1 <= grow0 + 8) ? __expf(sacc[j][3] * 0.125f) : 0.f;
                lsum0 += p0 + p1;
                lsum1 += p2 + p3;
                *(float2*)(attn + (size_t)grow0 * S_LEN + cj)       = make_float2(p0, p1);
                *(float2*)(attn + (size_t)(grow0 + 8) * S_LEN + cj) = make_float2(p2, p3);
                uint32_t h0 = bf2(p0, p1), h1 = bf2(p2, p3);
                ah[2 * jj]     = h0;
                ah[2 * jj + 1] = h1;
                al[2 * jj]     = bf2(p0 - bflo(h0), p1 - bfhi(h0));
                al[2 * jj + 1] = bf2(p2 - bflo(h1), p3 - bfhi(h1));
            }
            #pragma unroll
            for (int jp = 0; jp < 4; jp++) {
                uint32_t vh[4], vl[4];
                uint32_t boff = bVbase + (uint32_t)(ks * 16 * RS + jp * 32);
                ldsm_x4t(vh, smb + OFF_VHI + boff);
                ldsm_x4t(vl, smb + OFF_VLO + boff);
                mma16816(oacc[2 * jp],     ah, vh);
                mma16816(oacc[2 * jp + 1], ah, vh + 2);
                mma16816(oacc[2 * jp],     ah, vl);
                mma16816(oacc[2 * jp + 1], ah, vl + 2);
                mma16816(oacc[2 * jp],     al, vh);
                mma16816(oacc[2 * jp + 1], al, vh + 2);
            }
        }
    }

    // ---- reduce row sums within quads, normalize O, write context ----
    lsum0 += __shfl_xor_sync(0xffffffffu, lsum0, 1);
    lsum0 += __shfl_xor_sync(0xffffffffu, lsum0, 2);
    lsum1 += __shfl_xor_sync(0xffffffffu, lsum1, 1);
    lsum1 += __shfl_xor_sync(0xffffffffu, lsum1, 2);
    const float inv0 = 1.f / lsum0;
    const float inv1 = 1.f / lsum1;
    if (q == 0) {
        sinv[mrow + r]     = inv0;
        sinv[mrow + r + 8] = inv1;
    }
    #pragma unroll
    for (int j = 0; j < 8; j++) {
        int cj = j * 8 + q * 2;
        *(float2*)(ctx + (size_t)grow0 * DK + cj) =
            make_float2(oacc[j][0] * inv0, oacc[j][1] * inv0);
        *(float2*)(ctx + (size_t)(grow0 + 8) * DK + cj) =
            make_float2(oacc[j][2] * inv1, oacc[j][3] * inv1);
    }

    // ---- tail: normalize own attn rows + zero upper triangle ----
    // __syncthreads orders this CTA's prior global writes for re-read.
    __syncthreads();
    for (int rr = 0; rr < BM; rr++) {
        const int grow = row0 + rr;
        const float inv = sinv[rr];
        float4* rowp = (float4*)(attn + (size_t)grow * S_LEN);
        #pragma unroll
        for (int it = 0; it < 2; it++) {
            int c4  = tid + it * 256;
            int col = c4 << 2;
            float4 v;
            if (col + 3 <= grow) {                  // fully unmasked: scale
                v = rowp[c4];
                v.x *= inv; v.y *= inv; v.z *= inv; v.w *= inv;
            } else if (col > grow) {                // fully masked: zero, no read
                v.x = 0.f; v.y = 0.f; v.z = 0.f; v.w = 0.f;
            } else {                                // straddles diagonal
                v = rowp[c4];
                v.x = (col + 0 <= grow) ? v.x * inv : 0.f;
                v.y = (col + 1 <= grow) ? v.y * inv : 0.f;
                v.z = (col + 2 <= grow) ? v.z * inv : 0.f;
                v.w = (col + 3 <= grow) ? v.w * inv : 0.f;
            }
            __stcs(rowp + c4, v);                   // final value, streaming
        }
    }
}

extern "C" void kernel_launch(void* const* d_in, const int* in_sizes, int n_in,
                              void* d_out, int out_size)
{
    const float* Q = (const float*)d_in[0];
    const float* K = (const float*)d_in[1];
    const float* V = (const float*)d_in[2];
    float* out = (float*)d_out;

    cudaFuncSetAttribute(attn_fused, cudaFuncAttributeMaxDynamicSharedMemorySize,
                         SMEM_TOTAL);

    dim3 grid1(S_LEN / BM, NBH);
    attn_fused<<<grid1, 256, SMEM_TOTAL>>>(Q, K, V, out);
}

// round 14
// speedup vs baseline: 1.1269x; 1.1269x over previous
#include <cuda_runtime.h>
#include <cstdint>

#define S_LEN 2048
#define DK 64
#define BM 128
#define BN 64
#define NBH 32
#define CTX_ELEMS ((size_t)NBH * S_LEN * DK)

#define RS 144   // smem row stride in bytes -> conflict-free LDSM

#define OFF_QHI 0
#define OFF_QLO (BM * RS)
#define OFF_KHI (2 * BM * RS)
#define OFF_KLO (OFF_KHI + BN * RS)
#define OFF_VHI (OFF_KLO + BN * RS)
#define OFF_VLO (OFF_VHI + BN * RS)
#define SMEM_TOTAL (OFF_VLO + BN * RS)   // 73728 B -> 2 CTAs/SM

__device__ float g_lsum[NBH * S_LEN];

// ---------------------------------------------------------------------------
// helpers
// ---------------------------------------------------------------------------
__device__ __forceinline__ uint32_t smem_u32(const void* p) {
    uint32_t a;
    asm("{ .reg .u64 t; cvta.to.shared.u64 t, %1; cvt.u32.u64 %0, t; }"
        : "=r"(a) : "l"(p));
    return a;
}

__device__ __forceinline__ void ldsm_x4(uint32_t* r, uint32_t addr) {
    asm volatile("ldmatrix.sync.aligned.m8n8.x4.shared.b16 {%0,%1,%2,%3}, [%4];"
        : "=r"(r[0]), "=r"(r[1]), "=r"(r[2]), "=r"(r[3]) : "r"(addr));
}
__device__ __forceinline__ void ldsm_x4t(uint32_t* r, uint32_t addr) {
    asm volatile("ldmatrix.sync.aligned.m8n8.x4.trans.shared.b16 {%0,%1,%2,%3}, [%4];"
        : "=r"(r[0]), "=r"(r[1]), "=r"(r[2]), "=r"(r[3]) : "r"(addr));
}

// pack two f32 -> bf16x2 (a -> low half, b -> high half)
__device__ __forceinline__ uint32_t bf2(float a, float b) {
    uint32_t r;
    asm("cvt.rn.bf16x2.f32 %0, %1, %2;" : "=r"(r) : "f"(b), "f"(a));
    return r;
}
__device__ __forceinline__ float bflo(uint32_t p) { return __uint_as_float(p << 16); }
__device__ __forceinline__ float bfhi(uint32_t p) { return __uint_as_float(p & 0xffff0000u); }

// m16n8k16 bf16 mma, D=C. NOT volatile: pure register op, lets ptxas schedule.
__device__ __forceinline__ void mma16816(float* c, const uint32_t* a, const uint32_t* b) {
    asm("mma.sync.aligned.m16n8k16.row.col.f32.bf16.bf16.f32 "
        "{%0,%1,%2,%3}, {%4,%5,%6,%7}, {%8,%9}, {%0,%1,%2,%3};"
        : "+f"(c[0]), "+f"(c[1]), "+f"(c[2]), "+f"(c[3])
        : "r"(a[0]), "r"(a[1]), "r"(a[2]), "r"(a[3]), "r"(b[0]), "r"(b[1]));
}

// 6 MMAs of one 16-key group into accumulator pair (i0, i1).
// Order per accumulator: hh, hl, lh  (bit-identical to prior rounds).
#define MMA6(ACC, i0, i1, AH, AL, BH, BL) do {      \
    mma16816((ACC)[i0], AH, BH);                    \
    mma16816((ACC)[i1], AH, (BH) + 2);              \
    mma16816((ACC)[i0], AH, BL);                    \
    mma16816((ACC)[i1], AH, (BL) + 2);              \
    mma16816((ACC)[i0], AL, BH);                    \
    mma16816((ACC)[i1], AL, (BH) + 2);              \
} while (0)

// convert 8 f32 (two float4) -> hi/lo bf16 16B chunks, store linear
__device__ __forceinline__ void cvt_store8(float4 a, float4 b, char* hi_base,
                                           char* lo_base, uint32_t byte_off) {
    float x[8] = {a.x, a.y, a.z, a.w, b.x, b.y, b.z, b.w};
    uint4 hi4, lo4;
    uint32_t* hp = (uint32_t*)&hi4;
    uint32_t* lp = (uint32_t*)&lo4;
    #pragma unroll
    for (int i = 0; i < 4; i++) {
        uint32_t h = bf2(x[2 * i], x[2 * i + 1]);
        hp[i] = h;
        lp[i] = bf2(x[2 * i] - bflo(h), x[2 * i + 1] - bfhi(h));
    }
    *(uint4*)(hi_base + byte_off) = hi4;
    *(uint4*)(lo_base + byte_off) = lo4;
}

// ---------------------------------------------------------------------------
// Pass 1: mma.sync flash attention; unnormalized attn + normalized context.
// CTA = 256 threads (8 warps); warp w owns rows [w*16, w*16+16).
// Fragment loads software-pipelined with explicit double buffers.
// ---------------------------------------------------------------------------
__global__ __launch_bounds__(256, 2)
void attn_pass1(const float* __restrict__ Qg, const float* __restrict__ Kg,
                const float* __restrict__ Vg, float* __restrict__ out)
{
    extern __shared__ char smc[];
    const uint32_t smb = smem_u32(smc);
    const int tid  = threadIdx.x;
    const int wid  = tid >> 5;
    const int lane = tid & 31;
    const int r    = lane >> 2;     // C/A fragment row-in-group
    const int q    = lane & 3;      // fragment col-group

    const int bh   = blockIdx.y;
    const int qb   = (int)gridDim.x - 1 - (int)blockIdx.x;  // heavy blocks first
    const int row0 = qb * BM;
    const int mrow = wid * 16;

    const float* Qbh = Qg + (size_t)bh * S_LEN * DK;
    const float* Kbh = Kg + (size_t)bh * S_LEN * DK;
    const float* Vbh = Vg + (size_t)bh * S_LEN * DK;
    float* ctx  = out + (size_t)bh * S_LEN * DK;
    float* attn = out + CTX_ELEMS + (size_t)bh * S_LEN * S_LEN;

    // per-lane ldmatrix base offsets
    const uint32_t aQbase = (uint32_t)((mrow + (lane & 15)) * RS + (lane >> 4) * 16);
    const uint32_t bKbase = (uint32_t)(((lane >> 4) * 8 + (lane & 7)) * RS
                                       + ((lane >> 3) & 1) * 16);
    const uint32_t bVbase = (uint32_t)((((lane >> 3) & 1) * 8 + (lane & 7)) * RS
                                       + (lane >> 4) * 16);

    // ---- convert Q tile (2 threads per row, 32 elems each) ----
    {
        int row = tid >> 1, half = tid & 1;
        const float* qrow = Qbh + (size_t)(row0 + row) * DK + half * 32;
        #pragma unroll
        for (int g = 0; g < 4; g++) {
            float4 a = __ldg((const float4*)(qrow + g * 8));
            float4 b = __ldg((const float4*)(qrow + g * 8 + 4));
            cvt_store8(a, b, smc + OFF_QHI, smc + OFF_QLO,
                       (uint32_t)(row * RS + half * 64 + g * 16));
        }
    }

    float oacc[8][4];
    #pragma unroll
    for (int j = 0; j < 8; j++) {
        oacc[j][0] = 0.f; oacc[j][1] = 0.f; oacc[j][2] = 0.f; oacc[j][3] = 0.f;
    }
    float lsum0 = 0.f, lsum1 = 0.f;
    const int grow0  = row0 + mrow + r;         // this thread's first row
    const int rowmax = row0 + mrow + 15;        // warp band's last row

    // K/V gmem positions for this thread (4 threads per row, 16 floats each)
    const int ld_row = tid >> 2;
    const int ld_qt  = tid & 3;

    const int nkb = 2 * qb + 2;
    for (int jb = 0; jb < nkb; jb++) {
        const int c0 = jb * BN;

        // ---- issue gmem loads BEFORE the barrier (latency overlap) ----
        const float* krow = Kbh + (size_t)(c0 + ld_row) * DK + ld_qt * 16;
        const float* vrow = Vbh + (size_t)(c0 + ld_row) * DK + ld_qt * 16;
        float4 k0 = __ldg((const float4*)(krow));
        float4 k1 = __ldg((const float4*)(krow + 4));
        float4 k2 = __ldg((const float4*)(krow + 8));
        float4 k3 = __ldg((const float4*)(krow + 12));
        float4 v0 = __ldg((const float4*)(vrow));
        float4 v1 = __ldg((const float4*)(vrow + 4));
        float4 v2 = __ldg((const float4*)(vrow + 8));
        float4 v3 = __ldg((const float4*)(vrow + 12));

        if (jb) __syncthreads();                // prior tile done with K/V smem

        {
            uint32_t off = (uint32_t)(ld_row * RS + ld_qt * 32);
            cvt_store8(k0, k1, smc + OFF_KHI, smc + OFF_KLO, off);
            cvt_store8(k2, k3, smc + OFF_KHI, smc + OFF_KLO, off + 16);
            cvt_store8(v0, v1, smc + OFF_VHI, smc + OFF_VLO, off);
            cvt_store8(v2, v3, smc + OFF_VHI, smc + OFF_VLO, off + 16);
        }
        __syncthreads();

        if (c0 > rowmax) continue;              // tile fully masked for warp

        // number of active 16-key groups for this warp (warp-uniform, 1..4)
        const int njp = min(4, ((rowmax - c0) >> 4) + 1);

        // ---- S = Q @ K^T (split-bf16, pipelined K-fragment loads) ----
        float sacc[8][4];
        #pragma unroll
        for (int j = 0; j < 8; j++) {
            sacc[j][0] = 0.f; sacc[j][1] = 0.f; sacc[j][2] = 0.f; sacc[j][3] = 0.f;
        }
        #pragma unroll
        for (int ks = 0; ks < 4; ks++) {
            uint32_t ah[4], al[4];
            ldsm_x4(ah, smb + OFF_QHI + aQbase + ks * 32);
            ldsm_x4(al, smb + OFF_QLO + aQbase + ks * 32);
            const uint32_t kb = bKbase + (uint32_t)(ks * 32);
            uint32_t khA[4], klA[4], khB[4], klB[4];
            ldsm_x4(khA, smb + OFF_KHI + kb);
            ldsm_x4(klA, smb + OFF_KLO + kb);
            if (njp > 1) {
                ldsm_x4(khB, smb + OFF_KHI + kb + 16 * RS);
                ldsm_x4(klB, smb + OFF_KLO + kb + 16 * RS);
            }
            MMA6(sacc, 0, 1, ah, al, khA, klA);
            if (njp > 1) {
                if (njp > 2) {
                    ldsm_x4(khA, smb + OFF_KHI + kb + 32 * RS);
                    ldsm_x4(klA, smb + OFF_KLO + kb + 32 * RS);
                }
                MMA6(sacc, 2, 3, ah, al, khB, klB);
                if (njp > 2) {
                    if (njp > 3) {
                        ldsm_x4(khB, smb + OFF_KHI + kb + 48 * RS);
                        ldsm_x4(klB, smb + OFF_KLO + kb + 48 * RS);
                    }
                    MMA6(sacc, 4, 5, ah, al, khA, klA);
                    if (njp > 3) MMA6(sacc, 6, 7, ah, al, khB, klB);
                }
            }
        }

        // ---- fused epilogue + PV (pipelined V-fragment loads) ----
        uint32_t vhA[4], vlA[4], vhB[4], vlB[4];
        ldsm_x4t(vhA, smb + OFF_VHI + bVbase);          // (g=0, jp=0)
        ldsm_x4t(vlA, smb + OFF_VLO + bVbase);
        #pragma unroll
        for (int g = 0; g < 4; g++) {
            if (g >= njp) break;                         // masked groups: P == 0
            uint32_t ah[4], al[4];
            #pragma unroll
            for (int jj = 0; jj < 2; jj++) {
                const int j  = 2 * g + jj;
                const int cj = c0 + j * 8 + q * 2;
                float p0 = (cj     <= grow0)     ? __expf(sacc[j][0] * 0.125f) : 0.f;
                float p1 = (cj + 1 <= grow0)     ? __expf(sacc[j][1] * 0.125f) : 0.f;
                float p2 = (cj     <= grow0 + 8) ? __expf(sacc[j][2] * 0.125f) : 0.f;
                float p3 = (cj + 1 <= grow0 + 8) ? __expf(sacc[j][3] * 0.125f) : 0.f;
                lsum0 += p0 + p1;
                lsum1 += p2 + p3;
                *(float2*)(attn + (size_t)grow0 * S_LEN + cj)       = make_float2(p0, p1);
                *(float2*)(attn + (size_t)(grow0 + 8) * S_LEN + cj) = make_float2(p2, p3);
                uint32_t h0 = bf2(p0, p1), h1 = bf2(p2, p3);
                ah[2 * jj]     = h0;
                ah[2 * jj + 1] = h1;
                al[2 * jj]     = bf2(p0 - bflo(h0), p1 - bfhi(h0));
                al[2 * jj + 1] = bf2(p2 - bflo(h1), p3 - bfhi(h1));
            }
            const uint32_t vb = bVbase + (uint32_t)(g * 16 * RS);
            ldsm_x4t(vhB, smb + OFF_VHI + vb + 32);
            ldsm_x4t(vlB, smb + OFF_VLO + vb + 32);
            MMA6(oacc, 0, 1, ah, al, vhA, vlA);
            ldsm_x4t(vhA, smb + OFF_VHI + vb + 64);
            ldsm_x4t(vlA, smb + OFF_VLO + vb + 64);
            MMA6(oacc, 2, 3, ah, al, vhB, vlB);
            ldsm_x4t(vhB, smb + OFF_VHI + vb + 96);
            ldsm_x4t(vlB, smb + OFF_VLO + vb + 96);
            MMA6(oacc, 4, 5, ah, al, vhA, vlA);
            if (g + 1 < njp) {
                ldsm_x4t(vhA, smb + OFF_VHI + bVbase + (uint32_t)((g + 1) * 16 * RS));
                ldsm_x4t(vlA, smb + OFF_VLO + bVbase + (uint32_t)((g + 1) * 16 * RS));
            }
            MMA6(oacc, 6, 7, ah, al, vhB, vlB);
        }
    }

    // ---- reduce row sums within quads, normalize O, write context ----
    lsum0 += __shfl_xor_sync(0xffffffffu, lsum0, 1);
    lsum0 += __shfl_xor_sync(0xffffffffu, lsum0, 2);
    lsum1 += __shfl_xor_sync(0xffffffffu, lsum1, 1);
    lsum1 += __shfl_xor_sync(0xffffffffu, lsum1, 2);
    if (q == 0) {
        g_lsum[bh * S_LEN + grow0]     = lsum0;
        g_lsum[bh * S_LEN + grow0 + 8] = lsum1;
    }
    const float inv0 = 1.f / lsum0;
    const float inv1 = 1.f / lsum1;
    #pragma unroll
    for (int j = 0; j < 8; j++) {
        int cj = j * 8 + q * 2;
        *(float2*)(ctx + (size_t)grow0 * DK + cj) =
            make_float2(oacc[j][0] * inv0, oacc[j][1] * inv0);
        *(float2*)(ctx + (size_t)(grow0 + 8) * DK + cj) =
            make_float2(oacc[j][2] * inv1, oacc[j][3] * inv1);
    }
}

// ---------------------------------------------------------------------------
// Pass 2: attn[row, col<=row] *= 1/l(row); attn[row, col>row] = 0.
// ---------------------------------------------------------------------------
__global__ __launch_bounds__(256)
void attn_pass2(float* __restrict__ out)
{
    const int gid = blockIdx.x;               // bh*S_LEN + row
    const int r   = gid & (S_LEN - 1);
    const float inv = 1.f / g_lsum[gid];
    float4* rowp = (float4*)(out + CTX_ELEMS + (size_t)gid * S_LEN);
    const int tid = threadIdx.x;

    #pragma unroll
    for (int it = 0; it < 2; it++) {
        int c4  = tid + it * 256;
        int col = c4 << 2;
        float4 v;
        if (col + 3 <= r) {
            v = __ldcs(rowp + c4);
            v.x *= inv; v.y *= inv; v.z *= inv; v.w *= inv;
        } else if (col > r) {
            v.x = 0.f; v.y = 0.f; v.z = 0.f; v.w = 0.f;
        } else {
            v = __ldcs(rowp + c4);
            v.x = (col + 0 <= r) ? v.x * inv : 0.f;
            v.y = (col + 1 <= r) ? v.y * inv : 0.f;
            v.z = (col + 2 <= r) ? v.z * inv : 0.f;
            v.w = (col + 3 <= r) ? v.w * inv : 0.f;
        }
        __stcs(rowp + c4, v);
    }
}

extern "C" void kernel_launch(void* const* d_in, const int* in_sizes, int n_in,
                              void* d_out, int out_size)
{
    const float* Q = (const float*)d_in[0];
    const float* K = (const float*)d_in[1];
    const float* V = (const float*)d_in[2];
    float* out = (float*)d_out;

    cudaFuncSetAttribute(attn_pass1, cudaFuncAttributeMaxDynamicSharedMemorySize,
                         SMEM_TOTAL);

    dim3 grid1(S_LEN / BM, NBH);
    attn_pass1<<<grid1, 256, SMEM_TOTAL>>>(Q, K, V, out);
    attn_pass2<<<NBH * S_LEN, 256>>>(out);
}

// round 17
// speedup vs baseline: 1.1281x; 1.0010x over previous
#include <cuda_runtime.h>
#include <cstdint>

#define S_LEN 2048
#define DK 64
#define BM 128
#define BN 64
#define NBH 32
#define CTX_ELEMS ((size_t)NBH * S_LEN * DK)

#define RS 144   // smem row stride in bytes -> conflict-free LDSM

#define OFF_QHI 0
#define OFF_QLO (BM * RS)
#define OFF_KHI (2 * BM * RS)
#define OFF_KLO (OFF_KHI + BN * RS)
#define OFF_VHI (OFF_KLO + BN * RS)
#define OFF_VLO (OFF_VHI + BN * RS)
#define SMEM_TOTAL (OFF_VLO + BN * RS)   // 73728 B -> 2 CTAs/SM

__device__ float g_lsum[NBH * S_LEN];

// ---------------------------------------------------------------------------
// helpers
// ---------------------------------------------------------------------------
__device__ __forceinline__ uint32_t smem_u32(const void* p) {
    uint32_t a;
    asm("{ .reg .u64 t; cvta.to.shared.u64 t, %1; cvt.u32.u64 %0, t; }"
        : "=r"(a) : "l"(p));
    return a;
}

__device__ __forceinline__ void ldsm_x4(uint32_t* r, uint32_t addr) {
    asm volatile("ldmatrix.sync.aligned.m8n8.x4.shared.b16 {%0,%1,%2,%3}, [%4];"
        : "=r"(r[0]), "=r"(r[1]), "=r"(r[2]), "=r"(r[3]) : "r"(addr));
}
__device__ __forceinline__ void ldsm_x4t(uint32_t* r, uint32_t addr) {
    asm volatile("ldmatrix.sync.aligned.m8n8.x4.trans.shared.b16 {%0,%1,%2,%3}, [%4];"
        : "=r"(r[0]), "=r"(r[1]), "=r"(r[2]), "=r"(r[3]) : "r"(addr));
}

// pack two f32 -> bf16x2 (a -> low half, b -> high half)
__device__ __forceinline__ uint32_t bf2(float a, float b) {
    uint32_t r;
    asm("cvt.rn.bf16x2.f32 %0, %1, %2;" : "=r"(r) : "f"(b), "f"(a));
    return r;
}
__device__ __forceinline__ float bflo(uint32_t p) { return __uint_as_float(p << 16); }
__device__ __forceinline__ float bfhi(uint32_t p) { return __uint_as_float(p & 0xffff0000u); }

// m16n8k16 bf16 mma, D=C. NOT volatile: pure register op, lets ptxas schedule.
__device__ __forceinline__ void mma16816(float* c, const uint32_t* a, const uint32_t* b) {
    asm("mma.sync.aligned.m16n8k16.row.col.f32.bf16.bf16.f32 "
        "{%0,%1,%2,%3}, {%4,%5,%6,%7}, {%8,%9}, {%0,%1,%2,%3};"
        : "+f"(c[0]), "+f"(c[1]), "+f"(c[2]), "+f"(c[3])
        : "r"(a[0]), "r"(a[1]), "r"(a[2]), "r"(a[3]), "r"(b[0]), "r"(b[1]));
}

// 6 MMAs of one 16-key group into accumulator pair (i0, i1).
// Order per accumulator: hh, hl, lh  (bit-identical to prior rounds).
#define MMA6(ACC, i0, i1, AH, AL, BH, BL) do {      \
    mma16816((ACC)[i0], AH, BH);                    \
    mma16816((ACC)[i1], AH, (BH) + 2);              \
    mma16816((ACC)[i0], AH, BL);                    \
    mma16816((ACC)[i1], AH, (BL) + 2);              \
    mma16816((ACC)[i0], AL, BH);                    \
    mma16816((ACC)[i1], AL, (BH) + 2);              \
} while (0)

// convert 8 f32 (two float4) -> hi/lo bf16 16B chunks, store linear
__device__ __forceinline__ void cvt_store8(float4 a, float4 b, char* hi_base,
                                           char* lo_base, uint32_t byte_off) {
    float x[8] = {a.x, a.y, a.z, a.w, b.x, b.y, b.z, b.w};
    uint4 hi4, lo4;
    uint32_t* hp = (uint32_t*)&hi4;
    uint32_t* lp = (uint32_t*)&lo4;
    #pragma unroll
    for (int i = 0; i < 4; i++) {
        uint32_t h = bf2(x[2 * i], x[2 * i + 1]);
        hp[i] = h;
        lp[i] = bf2(x[2 * i] - bflo(h), x[2 * i + 1] - bfhi(h));
    }
    *(uint4*)(hi_base + byte_off) = hi4;
    *(uint4*)(lo_base + byte_off) = lo4;
}

// ---------------------------------------------------------------------------
// Pass 1: mma.sync flash attention; unnormalized attn + normalized context.
// CTA = 256 threads (8 warps); warp w owns rows [w*16, w*16+16).
// Each warp also zero-fills its band's upper-triangle attn columns
// [band+16, S) so pass2 only needs to touch the lower triangle.
// ---------------------------------------------------------------------------
__global__ __launch_bounds__(256, 2)
void attn_pass1(const float* __restrict__ Qg, const float* __restrict__ Kg,
                const float* __restrict__ Vg, float* __restrict__ out)
{
    extern __shared__ char smc[];
    const uint32_t smb = smem_u32(smc);
    const int tid  = threadIdx.x;
    const int wid  = tid >> 5;
    const int lane = tid & 31;
    const int r    = lane >> 2;     // C/A fragment row-in-group
    const int q    = lane & 3;      // fragment col-group

    const int bh   = blockIdx.y;
    const int qb   = (int)gridDim.x - 1 - (int)blockIdx.x;  // heavy blocks first
    const int row0 = qb * BM;
    const int mrow = wid * 16;

    const float* Qbh = Qg + (size_t)bh * S_LEN * DK;
    const float* Kbh = Kg + (size_t)bh * S_LEN * DK;
    const float* Vbh = Vg + (size_t)bh * S_LEN * DK;
    float* ctx  = out + (size_t)bh * S_LEN * DK;
    float* attn = out + CTX_ELEMS + (size_t)bh * S_LEN * S_LEN;

    // per-lane ldmatrix base offsets
    const uint32_t aQbase = (uint32_t)((mrow + (lane & 15)) * RS + (lane >> 4) * 16);
    const uint32_t bKbase = (uint32_t)(((lane >> 4) * 8 + (lane & 7)) * RS
                                       + ((lane >> 3) & 1) * 16);
    const uint32_t bVbase = (uint32_t)((((lane >> 3) & 1) * 8 + (lane & 7)) * RS
                                       + (lane >> 4) * 16);

    // ---- convert Q tile (2 threads per row, 32 elems each) ----
    {
        int row = tid >> 1, half = tid & 1;
        const float* qrow = Qbh + (size_t)(row0 + row) * DK + half * 32;
        #pragma unroll
        for (int g = 0; g < 4; g++) {
            float4 a = __ldg((const float4*)(qrow + g * 8));
            float4 b = __ldg((const float4*)(qrow + g * 8 + 4));
            cvt_store8(a, b, smc + OFF_QHI, smc + OFF_QLO,
                       (uint32_t)(row * RS + half * 64 + g * 16));
        }
    }

    // ---- zero-fill upper triangle for this warp's band ----
    // Band rows [row0+mrow, row0+mrow+16); epilogue covers cols [0, band+16)
    // (masked entries written 0 inside active groups). Fill the rest here.
    {
        const int band0 = row0 + mrow;
        const int c4s   = (band0 + 16) >> 2;   // multiple of 4
        const float4 z  = make_float4(0.f, 0.f, 0.f, 0.f);
        if (c4s < S_LEN / 4) {
            #pragma unroll 1
            for (int rr = 0; rr < 16; rr++) {
                float4* rowp = (float4*)(attn + (size_t)(band0 + rr) * S_LEN);
                for (int c4 = c4s + lane; c4 < S_LEN / 4; c4 += 32)
                    __stcs(rowp + c4, z);
            }
        }
    }

    float oacc[8][4];
    #pragma unroll
    for (int j = 0; j < 8; j++) {
        oacc[j][0] = 0.f; oacc[j][1] = 0.f; oacc[j][2] = 0.f; oacc[j][3] = 0.f;
    }
    float lsum0 = 0.f, lsum1 = 0.f;
    const int grow0  = row0 + mrow + r;         // this thread's first row
    const int rowmax = row0 + mrow + 15;        // warp band's last row

    // K/V gmem positions for this thread (4 threads per row, 16 floats each)
    const int ld_row = tid >> 2;
    const int ld_qt  = tid & 3;

    const int nkb = 2 * qb + 2;
    for (int jb = 0; jb < nkb; jb++) {
        const int c0 = jb * BN;

        // ---- issue gmem loads BEFORE the barrier (latency overlap) ----
        const float* krow = Kbh + (size_t)(c0 + ld_row) * DK + ld_qt * 16;
        const float* vrow = Vbh + (size_t)(c0 + ld_row) * DK + ld_qt * 16;
        float4 k0 = __ldg((const float4*)(krow));
        float4 k1 = __ldg((const float4*)(krow + 4));
        float4 k2 = __ldg((const float4*)(krow + 8));
        float4 k3 = __ldg((const float4*)(krow + 12));
        float4 v0 = __ldg((const float4*)(vrow));
        float4 v1 = __ldg((const float4*)(vrow + 4));
        float4 v2 = __ldg((const float4*)(vrow + 8));
        float4 v3 = __ldg((const float4*)(vrow + 12));

        if (jb) __syncthreads();                // prior tile done with K/V smem

        {
            uint32_t off = (uint32_t)(ld_row * RS + ld_qt * 32);
            cvt_store8(k0, k1, smc + OFF_KHI, smc + OFF_KLO, off);
            cvt_store8(k2, k3, smc + OFF_KHI, smc + OFF_KLO, off + 16);
            cvt_store8(v0, v1, smc + OFF_VHI, smc + OFF_VLO, off);
            cvt_store8(v2, v3, smc + OFF_VHI, smc + OFF_VLO, off + 16);
        }
        __syncthreads();

        if (c0 > rowmax) continue;              // tile fully masked for warp

        // number of active 16-key groups for this warp (warp-uniform, 1..4)
        const int njp = min(4, ((rowmax - c0) >> 4) + 1);

        // ---- S = Q @ K^T (split-bf16, pipelined K-fragment loads) ----
        float sacc[8][4];
        #pragma unroll
        for (int j = 0; j < 8; j++) {
            sacc[j][0] = 0.f; sacc[j][1] = 0.f; sacc[j][2] = 0.f; sacc[j][3] = 0.f;
        }
        #pragma unroll
        for (int ks = 0; ks < 4; ks++) {
            uint32_t ah[4], al[4];
            ldsm_x4(ah, smb + OFF_QHI + aQbase + ks * 32);
            ldsm_x4(al, smb + OFF_QLO + aQbase + ks * 32);
            const uint32_t kb = bKbase + (uint32_t)(ks * 32);
            uint32_t khA[4], klA[4], khB[4], klB[4];
            ldsm_x4(khA, smb + OFF_KHI + kb);
            ldsm_x4(klA, smb + OFF_KLO + kb);
            if (njp > 1) {
                ldsm_x4(khB, smb + OFF_KHI + kb + 16 * RS);
                ldsm_x4(klB, smb + OFF_KLO + kb + 16 * RS);
            }
            MMA6(sacc, 0, 1, ah, al, khA, klA);
            if (njp > 1) {
                if (njp > 2) {
                    ldsm_x4(khA, smb + OFF_KHI + kb + 32 * RS);
                    ldsm_x4(klA, smb + OFF_KLO + kb + 32 * RS);
                }
                MMA6(sacc, 2, 3, ah, al, khB, klB);
                if (njp > 2) {
                    if (njp > 3) {
                        ldsm_x4(khB, smb + OFF_KHI + kb + 48 * RS);
                        ldsm_x4(klB, smb + OFF_KLO + kb + 48 * RS);
                    }
                    MMA6(sacc, 4, 5, ah, al, khA, klA);
                    if (njp > 3) MMA6(sacc, 6, 7, ah, al, khB, klB);
                }
            }
        }

        // ---- fused epilogue + PV (pipelined V-fragment loads) ----
        uint32_t vhA[4], vlA[4], vhB[4], vlB[4];
        ldsm_x4t(vhA, smb + OFF_VHI + bVbase);          // (g=0, jp=0)
        ldsm_x4t(vlA, smb + OFF_VLO + bVbase);
        #pragma unroll
        for (int g = 0; g < 4; g++) {
            if (g >= njp) break;                         // masked groups: P == 0
            uint32_t ah[4], al[4];
            #pragma unroll
            for (int jj = 0; jj < 2; jj++) {
                const int j  = 2 * g + jj;
                const int cj = c0 + j * 8 + q * 2;
                float p0 = (cj     <= grow0)     ? __expf(sacc[j][0] * 0.125f) : 0.f;
                float p1 = (cj + 1 <= grow0)     ? __expf(sacc[j][1] * 0.125f) : 0.f;
                float p2 = (cj     <= grow0 + 8) ? __expf(sacc[j][2] * 0.125f) : 0.f;
                float p3 = (cj + 1 <= grow0 + 8) ? __expf(sacc[j][3] * 0.125f) : 0.f;
                lsum0 += p0 + p1;
                lsum1 += p2 + p3;
                *(float2*)(attn + (size_t)grow0 * S_LEN + cj)       = make_float2(p0, p1);
                *(float2*)(attn + (size_t)(grow0 + 8) * S_LEN + cj) = make_float2(p2, p3);
                uint32_t h0 = bf2(p0, p1), h1 = bf2(p2, p3);
                ah[2 * jj]     = h0;
                ah[2 * jj + 1] = h1;
                al[2 * jj]     = bf2(p0 - bflo(h0), p1 - bfhi(h0));
                al[2 * jj + 1] = bf2(p2 - bflo(h1), p3 - bfhi(h1));
            }
            const uint32_t vb = bVbase + (uint32_t)(g * 16 * RS);
            ldsm_x4t(vhB, smb + OFF_VHI + vb + 32);
            ldsm_x4t(vlB, smb + OFF_VLO + vb + 32);
            MMA6(oacc, 0, 1, ah, al, vhA, vlA);
            ldsm_x4t(vhA, smb + OFF_VHI + vb + 64);
            ldsm_x4t(vlA, smb + OFF_VLO + vb + 64);
            MMA6(oacc, 2, 3, ah, al, vhB, vlB);
            ldsm_x4t(vhB, smb + OFF_VHI + vb + 96);
            ldsm_x4t(vlB, smb + OFF_VLO + vb + 96);
            MMA6(oacc, 4, 5, ah, al, vhA, vlA);
            if (g + 1 < njp) {
                ldsm_x4t(vhA, smb + OFF_VHI + bVbase + (uint32_t)((g + 1) * 16 * RS));
                ldsm_x4t(vlA, smb + OFF_VLO + bVbase + (uint32_t)((g + 1) * 16 * RS));
            }
            MMA6(oacc, 6, 7, ah, al, vhB, vlB);
        }
    }

    // ---- reduce row sums within quads, normalize O, write context ----
    lsum0 += __shfl_xor_sync(0xffffffffu, lsum0, 1);
    lsum0 += __shfl_xor_sync(0xffffffffu, lsum0, 2);
    lsum1 += __shfl_xor_sync(0xffffffffu, lsum1, 1);
    lsum1 += __shfl_xor_sync(0xffffffffu, lsum1, 2);
    if (q == 0) {
        g_lsum[bh * S_LEN + grow0]     = lsum0;
        g_lsum[bh * S_LEN + grow0 + 8] = lsum1;
    }
    const float inv0 = 1.f / lsum0;
    const float inv1 = 1.f / lsum1;
    #pragma unroll
    for (int j = 0; j < 8; j++) {
        int cj = j * 8 + q * 2;
        *(float2*)(ctx + (size_t)grow0 * DK + cj) =
            make_float2(oacc[j][0] * inv0, oacc[j][1] * inv0);
        *(float2*)(ctx + (size_t)(grow0 + 8) * DK + cj) =
            make_float2(oacc[j][2] * inv1, oacc[j][3] * inv1);
    }
}

// ---------------------------------------------------------------------------
// Pass 2: lower triangle only — attn[row, col<=row] *= 1/l(row).
// Columns > row were already zeroed (by pass1 fill or epilogue mask).
// ---------------------------------------------------------------------------
__global__ __launch_bounds__(256)
void attn_pass2(float* __restrict__ out)
{
    const int gid = blockIdx.x;               // bh*S_LEN + row
    const int r   = gid & (S_LEN - 1);
    const float inv = 1.f / g_lsum[gid];
    float4* rowp = (float4*)(out + CTX_ELEMS + (size_t)gid * S_LEN);
    const int tid = threadIdx.x;
    const int c4lim = r >> 2;                 // last float4 touching col <= r

    for (int c4 = tid; c4 <= c4lim; c4 += 256) {
        int col = c4 << 2;
        float4 v = __ldcs(rowp + c4);
        if (col + 3 <= r) {                   // fully unmasked
            v.x *= inv; v.y *= inv; v.z *= inv; v.w *= inv;
        } else {                              // straddles diagonal
            v.x = (col + 0 <= r) ? v.x * inv : 0.f;
            v.y = (col + 1 <= r) ? v.y * inv : 0.f;
            v.z = (col + 2 <= r) ? v.z * inv : 0.f;
            v.w = (col + 3 <= r) ? v.w * inv : 0.f;
        }
        __stcs(rowp + c4, v);
    }
}

extern "C" void kernel_launch(void* const* d_in, const int* in_sizes, int n_in,
                              void* d_out, int out_size)
{
    const float* Q = (const float*)d_in[0];
    const float* K = (const float*)d_in[1];
    const float* V = (const float*)d_in[2];
    float* out = (float*)d_out;

    cudaFuncSetAttribute(attn_pass1, cudaFuncAttributeMaxDynamicSharedMemorySize,
                         SMEM_TOTAL);

    dim3 grid1(S_LEN / BM, NBH);
    attn_pass1<<<grid1, 256, SMEM_TOTAL>>>(Q, K, V, out);
    attn_pass2<<<NBH * S_LEN, 256>>>(out);
}